// round 6
// baseline (speedup 1.0000x reference)
#include <cuda_runtime.h>
#include <cuda_bf16.h>

#define IMG_S 4096
#define NDOTS 100
#define TILE_W 64
#define TILE_H 16
#define NTILES ((IMG_S / TILE_W) * (IMG_S / TILE_H))   // 16384
#define NTHREADS 256
#define NCTAS 888   // 148 SMs * 6 resident blocks

__global__ __launch_bounds__(NTHREADS)
void patch_dots_kernel(const float* __restrict__ patch,
                       const float* __restrict__ centers,
                       const float* __restrict__ radii,
                       const float* __restrict__ colors,
                       float* __restrict__ out)
{
    __shared__ float sxc[NDOTS];
    __shared__ float syc[NDOTS];
    __shared__ float sr2[NDOTS];
    __shared__ float scr[NDOTS];
    __shared__ float scg[NDOTS];
    __shared__ float scb[NDOTS];
    __shared__ unsigned s_isect[2][4];   // double-buffered per-tile masks
    __shared__ unsigned s_full[2][4];

    const int tid = threadIdx.x;

    // ---- Load dot parameters ONCE per persistent CTA (exact reference math) ----
    if (tid < NDOTS) {
        float cx = floorf(centers[2 * tid + 0] * (float)IMG_S);
        float cy = floorf(centers[2 * tid + 1] * (float)IMG_S);
        float r  = floorf(radii[tid] * ((float)IMG_S / 5.0f));
        sxc[tid] = cx;
        syc[tid] = cy;
        sr2[tid] = r * r;
        scr[tid] = colors[3 * tid + 0];
        scg[tid] = colors[3 * tid + 1];
        scb[tid] = colors[3 * tid + 2];
    }
    __syncthreads();

    // Per-thread quad geometry within a tile (constant across tiles)
    const int lx = (tid & 15) * 4;        // 0..60
    const int ly = tid >> 4;              // 0..15

    const unsigned plane_q = (IMG_S / 4) * IMG_S;
    const unsigned row_q   = IMG_S / 4;
    const float4* __restrict__ p4 = (const float4*)patch;
    float4* __restrict__ o4 = (float4*)out;

    int parity = 0;

    for (int t = blockIdx.x; t < NTILES; t += NCTAS, parity ^= 1) {
        const int tx0 = (t & 63) * TILE_W;
        const int ty0 = (t >> 6) * TILE_H;

        // ---- Cull this tile (warps 0..3 cover dots 0..127) ----
        if (tid < 128) {
            bool isect = false, full = false;
            if (tid < NDOTS) {
                float cx = sxc[tid], cy = syc[tid], r2 = sr2[tid];
                float x0 = (float)tx0, x1 = (float)(tx0 + TILE_W - 1);
                float y0 = (float)ty0, y1 = (float)(ty0 + TILE_H - 1);
                float nx = fminf(fmaxf(cx, x0), x1) - cx;
                float ny = fminf(fmaxf(cy, y0), y1) - cy;
                isect = fmaf(nx, nx, ny * ny) <= r2;
                float fxd = fmaxf(fabsf(x0 - cx), fabsf(x1 - cx));
                float fyd = fmaxf(fabsf(y0 - cy), fabsf(y1 - cy));
                full = fmaf(fxd, fxd, fyd * fyd) <= r2;
            }
            unsigned mi = __ballot_sync(0xFFFFFFFFu, isect);
            unsigned mf = __ballot_sync(0xFFFFFFFFu, full);
            if ((tid & 31) == 0) {
                s_isect[parity][tid >> 5] = mi;
                s_full[parity][tid >> 5]  = mf;
            }
        }
        __syncthreads();   // single barrier per tile (double-buffered masks)

        unsigned m0 = s_isect[parity][0], m1 = s_isect[parity][1];
        unsigned m2 = s_isect[parity][2], m3 = s_isect[parity][3];
        const unsigned f0 = s_full[parity][0], f1 = s_full[parity][1];
        const unsigned f2 = s_full[parity][2], f3 = s_full[parity][3];

        int jmax = -1;
        if (f3)      jmax = 96 + (31 - __clz(f3));
        else if (f2) jmax = 64 + (31 - __clz(f2));
        else if (f1) jmax = 32 + (31 - __clz(f1));
        else if (f0) jmax =      (31 - __clz(f0));

        const bool tile_full = (jmax >= 0);
        if (tile_full) {
            if (jmax >= 96)      { m0 = m1 = m2 = 0; m3 &= 0xFFFFFFFFu << (jmax - 96); }
            else if (jmax >= 64) { m0 = m1 = 0;      m2 &= 0xFFFFFFFFu << (jmax - 64); }
            else if (jmax >= 32) { m0 = 0;           m1 &= 0xFFFFFFFFu << (jmax - 32); }
            else                 {                   m0 &= 0xFFFFFFFFu <<  jmax;       }
        }

        const int x = tx0 + lx;
        const int y = ty0 + ly;
        const unsigned qidx = (unsigned)y * row_q + (unsigned)(x >> 2);

        const int survivors = __popc(m0) + __popc(m1) + __popc(m2) + __popc(m3);

        int i0 = -1, i1 = -1, i2 = -1, i3 = -1;

        if (tile_full && survivors == 1) {
            // Uniform tile: single covering dot and nothing above it.
            i0 = i1 = i2 = i3 = jmax;
        } else {
            const float fx = (float)x;
            const float fy = (float)y;

            // Prefetch patch quad early only when misses are possible.
            float4 pr, pg, pb;
            if (!tile_full) {
                pr = p4[qidx];
                pg = p4[qidx + plane_q];
                pb = p4[qidx + 2 * plane_q];
            }

            int hitmask = 0;
            unsigned mm;
            #define TEST_LANE(J, DXJ)                                          \
                if (!(hitmask & (1 << J))) {                                   \
                    float dx = (DXJ);                                          \
                    if (fmaf(dx, dx, dy2) <= r2) {                             \
                        hitmask |= (1 << J);                                   \
                        i##J = i;                                              \
                    }                                                          \
                }

            #define SCAN_WORD(MW, BASE)                                        \
                mm = (MW);                                                     \
                while (mm) {                                                   \
                    int b = 31 - __clz(mm);                                    \
                    int i = (BASE) + b;                                        \
                    float dy = fy - syc[i];                                    \
                    float dy2 = dy * dy;                                       \
                    float r2  = sr2[i];                                        \
                    float dx0 = fx - sxc[i];                                   \
                    TEST_LANE(0, dx0)                                          \
                    TEST_LANE(1, dx0 + 1.0f)                                   \
                    TEST_LANE(2, dx0 + 2.0f)                                   \
                    TEST_LANE(3, dx0 + 3.0f)                                   \
                    if (hitmask == 0xF) break;                                 \
                    mm &= ~(1u << b);                                          \
                }

            SCAN_WORD(m3, 96)
            if (hitmask != 0xF) { SCAN_WORD(m2, 64) }
            if (hitmask != 0xF) { SCAN_WORD(m1, 32) }
            if (hitmask != 0xF) { SCAN_WORD(m0, 0)  }
            #undef SCAN_WORD
            #undef TEST_LANE

            if (hitmask != 0xF) {
                // misses only possible when !tile_full (patch prefetched)
                float4 vr, vg, vb;
                vr.x = (i0 >= 0) ? scr[i0] : pr.x;
                vr.y = (i1 >= 0) ? scr[i1] : pr.y;
                vr.z = (i2 >= 0) ? scr[i2] : pr.z;
                vr.w = (i3 >= 0) ? scr[i3] : pr.w;
                vg.x = (i0 >= 0) ? scg[i0] : pg.x;
                vg.y = (i1 >= 0) ? scg[i1] : pg.y;
                vg.z = (i2 >= 0) ? scg[i2] : pg.z;
                vg.w = (i3 >= 0) ? scg[i3] : pg.w;
                vb.x = (i0 >= 0) ? scb[i0] : pb.x;
                vb.y = (i1 >= 0) ? scb[i1] : pb.y;
                vb.z = (i2 >= 0) ? scb[i2] : pb.z;
                vb.w = (i3 >= 0) ? scb[i3] : pb.w;
                o4[qidx]               = vr;
                o4[qidx + plane_q]     = vg;
                o4[qidx + 2 * plane_q] = vb;
                continue;
            }
        }

        // All four lanes hit: pure color stores via shared lookup.
        o4[qidx]               = make_float4(scr[i0], scr[i1], scr[i2], scr[i3]);
        o4[qidx + plane_q]     = make_float4(scg[i0], scg[i1], scg[i2], scg[i3]);
        o4[qidx + 2 * plane_q] = make_float4(scb[i0], scb[i1], scb[i2], scb[i3]);
    }
}

extern "C" void kernel_launch(void* const* d_in, const int* in_sizes, int n_in,
                              void* d_out, int out_size)
{
    const float* patch   = (const float*)d_in[0];
    const float* centers = (const float*)d_in[1];
    const float* radii   = (const float*)d_in[2];
    const float* colors  = (const float*)d_in[3];
    float* out = (float*)d_out;

    patch_dots_kernel<<<NCTAS, NTHREADS>>>(patch, centers, radii, colors, out);
}

// round 7
// speedup vs baseline: 1.1986x; 1.1986x over previous
#include <cuda_runtime.h>
#include <cuda_bf16.h>

#define IMG_S 4096
#define NDOTS 100
#define TILE_W 64
#define TILE_H 16
#define NTHREADS 256

__global__ __launch_bounds__(NTHREADS)
void patch_dots_kernel(const float* __restrict__ patch,
                       const float* __restrict__ centers,
                       const float* __restrict__ radii,
                       const float* __restrict__ colors,
                       float* __restrict__ out)
{
    // Compact per-tile work list, descending dot index (highest first).
    __shared__ float4 sgeo[NDOTS];   // {cx, cy, r2, -}
    __shared__ float4 scol[NDOTS];   // {r, g, b, -}
    __shared__ unsigned s_mf[4];     // full-cover ballots
    __shared__ unsigned s_aw[4];     // alive ballots
    __shared__ int s_cnt;
    __shared__ int s_jmax;

    const int tid  = threadIdx.x;
    const int lane = tid & 31;
    const int wrp  = tid >> 5;

    const int tx0 = (blockIdx.x & 63) * TILE_W;
    const int ty0 = (blockIdx.x >> 6) * TILE_H;

    // ================= Cull phase (warps 0..3 own dots 0..127) =================
    bool isect = false;
    float cx = 0.f, cy = 0.f, r2 = -1.f, ccr = 0.f, ccg = 0.f, ccb = 0.f;

    if (tid < 128) {
        bool full = false;
        if (tid < NDOTS) {
            cx = floorf(centers[2 * tid + 0] * (float)IMG_S);
            cy = floorf(centers[2 * tid + 1] * (float)IMG_S);
            float r = floorf(radii[tid] * ((float)IMG_S / 5.0f));
            r2 = r * r;
            ccr = colors[3 * tid + 0];
            ccg = colors[3 * tid + 1];
            ccb = colors[3 * tid + 2];

            float x0 = (float)tx0, x1 = (float)(tx0 + TILE_W - 1);
            float y0 = (float)ty0, y1 = (float)(ty0 + TILE_H - 1);
            float nx = fminf(fmaxf(cx, x0), x1) - cx;
            float ny = fminf(fmaxf(cy, y0), y1) - cy;
            isect = fmaf(nx, nx, ny * ny) <= r2;
            float fxd = fmaxf(fabsf(x0 - cx), fabsf(x1 - cx));
            float fyd = fmaxf(fabsf(y0 - cy), fabsf(y1 - cy));
            full = fmaf(fxd, fxd, fyd * fyd) <= r2;
        }
        unsigned mf = __ballot_sync(0xFFFFFFFFu, full);
        if (lane == 0) s_mf[wrp] = mf;
    }
    __syncthreads();

    unsigned aw = 0;
    bool alive = false;
    int jmax = -1;
    if (tid < 128) {
        const unsigned f0 = s_mf[0], f1 = s_mf[1], f2 = s_mf[2], f3 = s_mf[3];
        if (f3)      jmax = 96 + (31 - __clz(f3));
        else if (f2) jmax = 64 + (31 - __clz(f2));
        else if (f1) jmax = 32 + (31 - __clz(f1));
        else if (f0) jmax =      (31 - __clz(f0));

        alive = isect && (tid >= jmax);
        aw = __ballot_sync(0xFFFFFFFFu, alive);
        if (lane == 0) s_aw[wrp] = aw;
    }
    __syncthreads();

    if (tid < 128) {
        const unsigned a0 = s_aw[0], a1 = s_aw[1], a2 = s_aw[2], a3 = s_aw[3];
        const int T = __popc(a0) + __popc(a1) + __popc(a2) + __popc(a3);
        if (alive) {
            int base = 0;
            if (wrp > 0) base += __popc(a0);
            if (wrp > 1) base += __popc(a1);
            if (wrp > 2) base += __popc(a2);
            const int before = base + __popc(aw & ((1u << lane) - 1u));
            const int slot = T - 1 - before;          // descending dot index
            sgeo[slot] = make_float4(cx, cy, r2, 0.f);
            scol[slot] = make_float4(ccr, ccg, ccb, 0.f);
        }
        if (tid == 0) { s_cnt = T; s_jmax = jmax; }
    }
    __syncthreads();

    // ================= Pixel phase: one quad (4 px) per thread =================
    const int lx = (tid & 15) * 4;       // 0..60
    const int ly = tid >> 4;             // 0..15
    const int x  = tx0 + lx;
    const int y  = ty0 + ly;

    const unsigned plane_q = (IMG_S / 4) * IMG_S;
    const unsigned qidx = (unsigned)y * (IMG_S / 4) + (unsigned)(x >> 2);
    const float4* __restrict__ p4 = (const float4*)patch;
    float4* __restrict__ o4 = (float4*)out;

    const int cnt = s_cnt;
    const bool tfull = (s_jmax >= 0);

    float4 vr, vg, vb;

    if (tfull && cnt == 1) {
        // Uniform tile: single color everywhere.
        const float4 c = scol[0];
        vr = make_float4(c.x, c.x, c.x, c.x);
        vg = make_float4(c.y, c.y, c.y, c.y);
        vb = make_float4(c.z, c.z, c.z, c.z);
    } else {
        float4 pr, pg, pb;
        if (!tfull) {                      // misses possible → prefetch early
            pr = p4[qidx];
            pg = p4[qidx + plane_q];
            pb = p4[qidx + 2 * plane_q];
        }

        const float fx = (float)x;
        const float fy = (float)y;
        int i0 = -1, i1 = -1, i2 = -1, i3 = -1;

        #pragma unroll 1
        for (int j = 0; j < cnt; ++j) {
            const float4 g = sgeo[j];      // uniform index → LDS broadcast
            const float dy  = fy - g.y;
            const float dy2 = dy * dy;
            const float dx0 = fx - g.x;
            const float dx1 = dx0 + 1.0f;
            const float dx2 = dx0 + 2.0f;
            const float dx3 = dx0 + 3.0f;
            if (i0 < 0 && fmaf(dx0, dx0, dy2) <= g.z) i0 = j;
            if (i1 < 0 && fmaf(dx1, dx1, dy2) <= g.z) i1 = j;
            if (i2 < 0 && fmaf(dx2, dx2, dy2) <= g.z) i2 = j;
            if (i3 < 0 && fmaf(dx3, dx3, dy2) <= g.z) i3 = j;
            if ((i0 | i1 | i2 | i3) >= 0) break;   // all lanes resolved
        }

        // Resolve colors (clamped safe loads; selects pick patch on miss).
        const float4 c0 = scol[i0 < 0 ? 0 : i0];
        const float4 c1 = scol[i1 < 0 ? 0 : i1];
        const float4 c2 = scol[i2 < 0 ? 0 : i2];
        const float4 c3 = scol[i3 < 0 ? 0 : i3];
        vr.x = (i0 >= 0) ? c0.x : pr.x;
        vr.y = (i1 >= 0) ? c1.x : pr.y;
        vr.z = (i2 >= 0) ? c2.x : pr.z;
        vr.w = (i3 >= 0) ? c3.x : pr.w;
        vg.x = (i0 >= 0) ? c0.y : pg.x;
        vg.y = (i1 >= 0) ? c1.y : pg.y;
        vg.z = (i2 >= 0) ? c2.y : pg.z;
        vg.w = (i3 >= 0) ? c3.y : pg.w;
        vb.x = (i0 >= 0) ? c0.z : pb.x;
        vb.y = (i1 >= 0) ? c1.z : pb.y;
        vb.z = (i2 >= 0) ? c2.z : pb.z;
        vb.w = (i3 >= 0) ? c3.z : pb.w;
    }

    o4[qidx]               = vr;
    o4[qidx + plane_q]     = vg;
    o4[qidx + 2 * plane_q] = vb;
}

extern "C" void kernel_launch(void* const* d_in, const int* in_sizes, int n_in,
                              void* d_out, int out_size)
{
    const float* patch   = (const float*)d_in[0];
    const float* centers = (const float*)d_in[1];
    const float* radii   = (const float*)d_in[2];
    const float* colors  = (const float*)d_in[3];
    float* out = (float*)d_out;

    const int blocks = (IMG_S / TILE_W) * (IMG_S / TILE_H);   // 16384
    patch_dots_kernel<<<blocks, NTHREADS>>>(patch, centers, radii, colors, out);
}

// round 9
// speedup vs baseline: 1.3070x; 1.0905x over previous
#include <cuda_runtime.h>
#include <cuda_bf16.h>

#define IMG_S 4096
#define NDOTS 100
#define TILE_W 64
#define TILE_H 16
#define NTHREADS 256

__global__ __launch_bounds__(NTHREADS)
void patch_dots_kernel(const float* __restrict__ patch,
                       const float* __restrict__ centers,
                       const float* __restrict__ radii,
                       const float* __restrict__ colors,
                       float* __restrict__ out)
{
    // Compact per-tile work list, descending dot index (highest first).
    __shared__ float4 sgeo[NDOTS];   // {cx, cy, r2, -}
    __shared__ float4 scol[NDOTS];   // {r, g, b, -}
    __shared__ unsigned s_mf[4];     // full-cover ballots
    __shared__ unsigned s_aw[4];     // alive ballots
    __shared__ int s_cnt;
    __shared__ int s_jmax;

    const int tid  = threadIdx.x;
    const int lane = tid & 31;
    const int wrp  = tid >> 5;

    const int tx0 = (blockIdx.x & 63) * TILE_W;
    const int ty0 = (blockIdx.x >> 6) * TILE_H;

    // ================= Cull phase (warps 0..3 own dots 0..127) =================
    bool isect = false;
    float cx = 0.f, cy = 0.f, r2 = -1.f, ccr = 0.f, ccg = 0.f, ccb = 0.f;

    if (tid < 128) {
        bool full = false;
        if (tid < NDOTS) {
            cx = floorf(centers[2 * tid + 0] * (float)IMG_S);
            cy = floorf(centers[2 * tid + 1] * (float)IMG_S);
            float r = floorf(radii[tid] * ((float)IMG_S / 5.0f));
            r2 = r * r;
            ccr = colors[3 * tid + 0];
            ccg = colors[3 * tid + 1];
            ccb = colors[3 * tid + 2];

            float x0 = (float)tx0, x1 = (float)(tx0 + TILE_W - 1);
            float y0 = (float)ty0, y1 = (float)(ty0 + TILE_H - 1);
            float nx = fminf(fmaxf(cx, x0), x1) - cx;
            float ny = fminf(fmaxf(cy, y0), y1) - cy;
            isect = fmaf(nx, nx, ny * ny) <= r2;
            float fxd = fmaxf(fabsf(x0 - cx), fabsf(x1 - cx));
            float fyd = fmaxf(fabsf(y0 - cy), fabsf(y1 - cy));
            full = fmaf(fxd, fxd, fyd * fyd) <= r2;
        }
        unsigned mf = __ballot_sync(0xFFFFFFFFu, full);
        if (lane == 0) s_mf[wrp] = mf;
    }
    __syncthreads();

    unsigned aw = 0;
    bool alive = false;
    int jmax = -1;
    if (tid < 128) {
        const unsigned f0 = s_mf[0], f1 = s_mf[1], f2 = s_mf[2], f3 = s_mf[3];
        if (f3)      jmax = 96 + (31 - __clz(f3));
        else if (f2) jmax = 64 + (31 - __clz(f2));
        else if (f1) jmax = 32 + (31 - __clz(f1));
        else if (f0) jmax =      (31 - __clz(f0));

        alive = isect && (tid >= jmax);
        aw = __ballot_sync(0xFFFFFFFFu, alive);
        if (lane == 0) s_aw[wrp] = aw;
    }
    __syncthreads();

    if (tid < 128) {
        const unsigned a0 = s_aw[0], a1 = s_aw[1], a2 = s_aw[2], a3 = s_aw[3];
        const int T = __popc(a0) + __popc(a1) + __popc(a2) + __popc(a3);
        if (alive) {
            int base = 0;
            if (wrp > 0) base += __popc(a0);
            if (wrp > 1) base += __popc(a1);
            if (wrp > 2) base += __popc(a2);
            const int before = base + __popc(aw & ((1u << lane) - 1u));
            const int slot = T - 1 - before;          // descending dot index
            sgeo[slot] = make_float4(cx, cy, r2, 0.f);
            scol[slot] = make_float4(ccr, ccg, ccb, 0.f);
        }
        if (tid == 0) { s_cnt = T; s_jmax = jmax; }
    }
    __syncthreads();

    // ================= Pixel phase: one quad (4 px) per thread =================
    const int lx = (tid & 15) * 4;       // 0..60
    const int ly = tid >> 4;             // 0..15
    const int x  = tx0 + lx;
    const int y  = ty0 + ly;

    const unsigned plane_q = (IMG_S / 4) * IMG_S;
    const unsigned qidx = (unsigned)y * (IMG_S / 4) + (unsigned)(x >> 2);
    const float4* __restrict__ p4 = (const float4*)patch;
    float4* __restrict__ o4 = (float4*)out;

    const int cnt = s_cnt;

    float4 vr, vg, vb;

    if (s_jmax >= 0 && cnt == 1) {
        // Uniform tile: single color everywhere.
        const float4 c = scol[0];
        vr = make_float4(c.x, c.x, c.x, c.x);
        vg = make_float4(c.y, c.y, c.y, c.y);
        vb = make_float4(c.z, c.z, c.z, c.z);
    } else {
        const float fx = (float)x;
        const float fy = (float)y;
        int i0 = -1, i1 = -1, i2 = -1, i3 = -1;

        #pragma unroll 1
        for (int j = 0; j < cnt; ++j) {
            const float4 g = sgeo[j];      // uniform index → LDS broadcast
            const float dy  = fy - g.y;
            const float dy2 = dy * dy;
            const float dx0 = fx - g.x;
            const float dx1 = dx0 + 1.0f;
            const float dx2 = dx0 + 2.0f;
            const float dx3 = dx0 + 3.0f;
            if (i0 < 0 && fmaf(dx0, dx0, dy2) <= g.z) i0 = j;
            if (i1 < 0 && fmaf(dx1, dx1, dy2) <= g.z) i1 = j;
            if (i2 < 0 && fmaf(dx2, dx2, dy2) <= g.z) i2 = j;
            if (i3 < 0 && fmaf(dx3, dx3, dy2) <= g.z) i3 = j;
            if ((i0 | i1 | i2 | i3) >= 0) break;   // all lanes resolved
        }

        // Colors for resolved lanes (clamped indices are safe).
        const float4 c0 = scol[i0 < 0 ? 0 : i0];
        const float4 c1 = scol[i1 < 0 ? 0 : i1];
        const float4 c2 = scol[i2 < 0 ? 0 : i2];
        const float4 c3 = scol[i3 < 0 ? 0 : i3];
        vr = make_float4(c0.x, c1.x, c2.x, c3.x);
        vg = make_float4(c0.y, c1.y, c2.y, c3.y);
        vb = make_float4(c0.z, c1.z, c2.z, c3.z);

        // Demand-load patch ONLY if some lane is uncovered (~2% of quads).
        if ((i0 | i1 | i2 | i3) < 0) {
            const float4 pr = p4[qidx];
            const float4 pg = p4[qidx + plane_q];
            const float4 pb = p4[qidx + 2 * plane_q];
            if (i0 < 0) { vr.x = pr.x; vg.x = pg.x; vb.x = pb.x; }
            if (i1 < 0) { vr.y = pr.y; vg.y = pg.y; vb.y = pb.y; }
            if (i2 < 0) { vr.z = pr.z; vg.z = pg.z; vb.z = pb.z; }
            if (i3 < 0) { vr.w = pr.w; vg.w = pg.w; vb.w = pb.w; }
        }
    }

    // Streaming stores: output is write-once, never re-read by this kernel.
    __stcs(&o4[qidx],               vr);
    __stcs(&o4[qidx + plane_q],     vg);
    __stcs(&o4[qidx + 2 * plane_q], vb);
}

extern "C" void kernel_launch(void* const* d_in, const int* in_sizes, int n_in,
                              void* d_out, int out_size)
{
    const float* patch   = (const float*)d_in[0];
    const float* centers = (const float*)d_in[1];
    const float* radii   = (const float*)d_in[2];
    const float* colors  = (const float*)d_in[3];
    float* out = (float*)d_out;

    const int blocks = (IMG_S / TILE_W) * (IMG_S / TILE_H);   // 16384
    patch_dots_kernel<<<blocks, NTHREADS>>>(patch, centers, radii, colors, out);
}

// round 10
// speedup vs baseline: 1.3108x; 1.0029x over previous
#include <cuda_runtime.h>
#include <cuda_bf16.h>

#define IMG_S 4096
#define NDOTS 100
#define TILE_W 32
#define TILE_H 32
#define NTHREADS 256

__global__ __launch_bounds__(NTHREADS)
void patch_dots_kernel(const float* __restrict__ patch,
                       const float* __restrict__ centers,
                       const float* __restrict__ radii,
                       const float* __restrict__ colors,
                       float* __restrict__ out)
{
    // Compact per-tile work list, descending dot index (highest first).
    __shared__ float4 sgeo[NDOTS];   // {cx, cy, r2, -}
    __shared__ float4 scol[NDOTS];   // {r, g, b, -}
    __shared__ unsigned s_mi[4];     // intersect ballots
    __shared__ unsigned s_mf[4];     // full-cover ballots
    __shared__ int s_cnt;
    __shared__ int s_jmax;

    const int tid  = threadIdx.x;
    const int lane = tid & 31;
    const int wrp  = tid >> 5;

    const int tx0 = (blockIdx.x & 127) * TILE_W;   // 128 tiles per row
    const int ty0 = (blockIdx.x >> 7) * TILE_H;

    // ========== Cull phase 1: one ballot round (warps 0..3, dots 0..127) ==========
    float cx = 0.f, cy = 0.f, r2 = -1.f, ccr = 0.f, ccg = 0.f, ccb = 0.f;

    if (tid < 128) {
        bool isect = false, full = false;
        if (tid < NDOTS) {
            cx = floorf(centers[2 * tid + 0] * (float)IMG_S);
            cy = floorf(centers[2 * tid + 1] * (float)IMG_S);
            float r = floorf(radii[tid] * ((float)IMG_S / 5.0f));
            r2 = r * r;
            ccr = colors[3 * tid + 0];
            ccg = colors[3 * tid + 1];
            ccb = colors[3 * tid + 2];

            float x0 = (float)tx0, x1 = (float)(tx0 + TILE_W - 1);
            float y0 = (float)ty0, y1 = (float)(ty0 + TILE_H - 1);
            float nx = fminf(fmaxf(cx, x0), x1) - cx;
            float ny = fminf(fmaxf(cy, y0), y1) - cy;
            isect = fmaf(nx, nx, ny * ny) <= r2;
            float fxd = fmaxf(fabsf(x0 - cx), fabsf(x1 - cx));
            float fyd = fmaxf(fabsf(y0 - cy), fabsf(y1 - cy));
            full = fmaf(fxd, fxd, fyd * fyd) <= r2;
        }
        unsigned mi = __ballot_sync(0xFFFFFFFFu, isect);
        unsigned mf = __ballot_sync(0xFFFFFFFFu, full);
        if (lane == 0) { s_mi[wrp] = mi; s_mf[wrp] = mf; }
    }
    __syncthreads();

    // ========== Cull phase 2: derive jmax + slot locally, no extra ballot ==========
    if (tid < 128) {
        const unsigned f0 = s_mf[0], f1 = s_mf[1], f2 = s_mf[2], f3 = s_mf[3];
        int jmax = -1;
        if (f3)      jmax = 96 + (31 - __clz(f3));
        else if (f2) jmax = 64 + (31 - __clz(f2));
        else if (f1) jmax = 32 + (31 - __clz(f1));
        else if (f0) jmax =      (31 - __clz(f0));

        unsigned a0 = s_mi[0], a1 = s_mi[1], a2 = s_mi[2], a3 = s_mi[3];
        // clear bits below jmax (shadowed dots)
        if (jmax >= 96)      { a0 = a1 = a2 = 0; a3 &= 0xFFFFFFFFu << (jmax - 96); }
        else if (jmax >= 64) { a0 = a1 = 0;      a2 &= 0xFFFFFFFFu << (jmax - 64); }
        else if (jmax >= 32) { a0 = 0;           a1 &= 0xFFFFFFFFu << (jmax - 32); }
        else if (jmax >= 0)  {                   a0 &= 0xFFFFFFFFu <<  jmax;       }

        const unsigned myw = (wrp == 0) ? a0 : (wrp == 1) ? a1 : (wrp == 2) ? a2 : a3;
        const bool alive = (myw >> lane) & 1u;
        if (alive) {
            // slot = number of surviving dots with index > tid  (descending order)
            int slot = __popc(myw & (0xFFFFFFFEu << lane));
            if (wrp < 3) slot += __popc(a3);
            if (wrp < 2) slot += __popc(a2);
            if (wrp < 1) slot += __popc(a1);
            sgeo[slot] = make_float4(cx, cy, r2, 0.f);
            scol[slot] = make_float4(ccr, ccg, ccb, 0.f);
        }
        if (tid == 0) {
            s_cnt  = __popc(a0) + __popc(a1) + __popc(a2) + __popc(a3);
            s_jmax = jmax;
        }
    }
    __syncthreads();

    // ================= Pixel phase: one quad (4 px) per thread =================
    const int lx = (tid & 7) * 4;        // 0..28
    const int ly = tid >> 3;             // 0..31
    const int x  = tx0 + lx;
    const int y  = ty0 + ly;

    const unsigned plane_q = (IMG_S / 4) * IMG_S;
    const unsigned qidx = (unsigned)y * (IMG_S / 4) + (unsigned)(x >> 2);
    const float4* __restrict__ p4 = (const float4*)patch;
    float4* __restrict__ o4 = (float4*)out;

    const int cnt = s_cnt;

    float4 vr, vg, vb;

    if (s_jmax >= 0 && cnt == 1) {
        // Uniform tile: single color everywhere.
        const float4 c = scol[0];
        vr = make_float4(c.x, c.x, c.x, c.x);
        vg = make_float4(c.y, c.y, c.y, c.y);
        vb = make_float4(c.z, c.z, c.z, c.z);
    } else {
        const float fx = (float)x;
        const float fy = (float)y;
        int i0 = -1, i1 = -1, i2 = -1, i3 = -1;

        #pragma unroll 1
        for (int j = 0; j < cnt; ++j) {
            const float4 g = sgeo[j];      // uniform index → LDS broadcast
            const float dy  = fy - g.y;
            const float dy2 = dy * dy;
            const float dx0 = fx - g.x;
            const float dx1 = dx0 + 1.0f;
            const float dx2 = dx0 + 2.0f;
            const float dx3 = dx0 + 3.0f;
            if (i0 < 0 && fmaf(dx0, dx0, dy2) <= g.z) i0 = j;
            if (i1 < 0 && fmaf(dx1, dx1, dy2) <= g.z) i1 = j;
            if (i2 < 0 && fmaf(dx2, dx2, dy2) <= g.z) i2 = j;
            if (i3 < 0 && fmaf(dx3, dx3, dy2) <= g.z) i3 = j;
            if ((i0 | i1 | i2 | i3) >= 0) break;   // all lanes resolved
        }

        // Colors for resolved lanes (clamped indices are safe).
        const float4 c0 = scol[i0 < 0 ? 0 : i0];
        const float4 c1 = scol[i1 < 0 ? 0 : i1];
        const float4 c2 = scol[i2 < 0 ? 0 : i2];
        const float4 c3 = scol[i3 < 0 ? 0 : i3];
        vr = make_float4(c0.x, c1.x, c2.x, c3.x);
        vg = make_float4(c0.y, c1.y, c2.y, c3.y);
        vb = make_float4(c0.z, c1.z, c2.z, c3.z);

        // Demand-load patch ONLY if some lane is uncovered (~2% of quads).
        if ((i0 | i1 | i2 | i3) < 0) {
            const float4 pr = p4[qidx];
            const float4 pg = p4[qidx + plane_q];
            const float4 pb = p4[qidx + 2 * plane_q];
            if (i0 < 0) { vr.x = pr.x; vg.x = pg.x; vb.x = pb.x; }
            if (i1 < 0) { vr.y = pr.y; vg.y = pg.y; vb.y = pb.y; }
            if (i2 < 0) { vr.z = pr.z; vg.z = pg.z; vb.z = pb.z; }
            if (i3 < 0) { vr.w = pr.w; vg.w = pg.w; vb.w = pb.w; }
        }
    }

    // Streaming stores: output is write-once, never re-read by this kernel.
    __stcs(&o4[qidx],               vr);
    __stcs(&o4[qidx + plane_q],     vg);
    __stcs(&o4[qidx + 2 * plane_q], vb);
}

extern "C" void kernel_launch(void* const* d_in, const int* in_sizes, int n_in,
                              void* d_out, int out_size)
{
    const float* patch   = (const float*)d_in[0];
    const float* centers = (const float*)d_in[1];
    const float* radii   = (const float*)d_in[2];
    const float* colors  = (const float*)d_in[3];
    float* out = (float*)d_out;

    const int blocks = (IMG_S / TILE_W) * (IMG_S / TILE_H);   // 128 * 128 = 16384
    patch_dots_kernel<<<blocks, NTHREADS>>>(patch, centers, radii, colors, out);
}